// round 11
// baseline (speedup 1.0000x reference)
#include <cuda_runtime.h>
#include <cuda_bf16.h>

#define BATCH 512
#define NTOK  4096
#define NP1   4097
#define NTHR  512

#define CONTENT_PAD 1024.0f
#define CONTENT_EOS 1025.0f
#define COARSE_POS_PAD 128.0f
#define COARSE_POS_EOS 129.0f
#define MEDIUM_POS_PAD 256.0f
#define MEDIUM_POS_EOS 257.0f
#define FINE_POS_PAD 1024.0f
#define FINE_POS_EOS 1025.0f

// Copy cnt elems from two smem arrays (bases phase-matched to gmem alignment)
// to two gmem planes. Both sides use 128-bit accesses in the bulk.
__device__ __forceinline__ void copy_pair(float* __restrict__ pc, float* __restrict__ pp,
                                          const float* __restrict__ svb,
                                          const float* __restrict__ spb,
                                          int cnt, int t, int b_align)
{
    int vs = (4 - b_align) & 3;
    if (vs > cnt) vs = cnt;
    for (int j = t; j < vs; j += NTHR) { pc[j] = svb[j]; pp[j] = spb[j]; }
    const int nvec = (cnt - vs) >> 2;
    const float4* s4 = (const float4*)(svb + vs);   // 16B-aligned by construction
    const float4* q4 = (const float4*)(spb + vs);
    float4* c4 = (float4*)(pc + vs);
    float4* p4 = (float4*)(pp + vs);
    for (int c = t; c < nvec; c += NTHR) {
        c4[c] = s4[c];
        p4[c] = q4[c];
    }
    for (int j = vs + (nvec << 2) + t; j < cnt; j += NTHR) {
        pc[j] = svb[j]; pp[j] = spb[j];
    }
}

// EOS at cnt, PAD beyond, for two planes sharing cnt.
__device__ __forceinline__ void tail_pair(float* __restrict__ pc, float* __restrict__ pp,
                                          int cnt, float eosC, float padC,
                                          float eosP, float padP,
                                          int t, int b_align)
{
    if (t == 0) { pc[cnt] = eosC; pp[cnt] = eosP; }
    const int start = cnt + 1;
    int vs = start + ((4 - ((start + b_align) & 3)) & 3);
    if (vs > NP1) vs = NP1;
    for (int j = start + t; j < vs; j += NTHR) { pc[j] = padC; pp[j] = padP; }
    const int nvec = (NP1 - vs) >> 2;
    float4* c4 = (float4*)(pc + vs);
    float4* p4 = (float4*)(pp + vs);
    const float4 pcv = make_float4(padC, padC, padC, padC);
    const float4 ppv = make_float4(padP, padP, padP, padP);
    for (int c = t; c < nvec; c += NTHR) { c4[c] = pcv; p4[c] = ppv; }
    for (int j = vs + (nvec << 2) + t; j < NP1; j += NTHR) {
        pc[j] = padC; pp[j] = padP;
    }
}

// Three constant planes in one loop.
__device__ __forceinline__ void fill_const3(float* __restrict__ p0, float* __restrict__ p1,
                                            float* __restrict__ p2,
                                            int t, int b_align)
{
    const int vs = (4 - b_align) & 3;
    for (int j = t; j < vs; j += NTHR) { p0[j] = 0.0f; p1[j] = 1.0f; p2[j] = 2.0f; }
    const int nvec = (NP1 - vs) >> 2;
    float4* a4 = (float4*)(p0 + vs);
    float4* b4 = (float4*)(p1 + vs);
    float4* c4 = (float4*)(p2 + vs);
    const float4 v0 = make_float4(0.f, 0.f, 0.f, 0.f);
    const float4 v1 = make_float4(1.f, 1.f, 1.f, 1.f);
    const float4 v2 = make_float4(2.f, 2.f, 2.f, 2.f);
    for (int c = t; c < nvec; c += NTHR) { a4[c] = v0; b4[c] = v1; c4[c] = v2; }
    const int tail = vs + (nvec << 2);
    for (int j = tail + t; j < NP1; j += NTHR) { p0[j] = 0.0f; p1[j] = 1.0f; p2[j] = 2.0f; }
}

// Output: 9 sections, each [BATCH, NP1] float32, tuple order:
//  0 coarse_content, 1 medium_content, 2 fine_content,
//  3 coarse_position, 4 medium_position, 5 fine_position,
//  6 coarse_segment,  7 medium_segment,  8 fine_segment
__global__ __launch_bounds__(NTHR, 3)
void triple_grain_kernel(const int* __restrict__ in0,
                         const int* __restrict__ in1,
                         float* __restrict__ out)
{
    __shared__ __align__(16) float sval[NTOK + 32];   // per-class aligned bases
    __shared__ __align__(16) float sposn[NTOK + 32];

    const int b = blockIdx.x;
    const int t = threadIdx.x;
    const unsigned lane = t & 31u;
    const unsigned warp = t >> 5;
    const int b_align = b & 3;          // row global elem offset mod 4 (4097*b ≡ b)

    const int4* a4 = (const int4*)(in0 + (long)b * NTOK);
    const int4* b4 = (const int4*)(in1 + (long)b * NTOK);

    // ---- phase 1: load, compute max(in0) + counts for BOTH interpretations ----
    unsigned a0 = 0, a1 = 0, b0 = 0, b1 = 0;
    int amax = 0;
    {
        int4 xa = a4[t * 2 + 0];
        int4 xb = a4[t * 2 + 1];
        int4 ya = b4[t * 2 + 0];
        int4 yb = b4[t * 2 + 1];
        int av[8] = {xa.x, xa.y, xa.z, xa.w, xb.x, xb.y, xb.z, xb.w};
        int bv[8] = {ya.x, ya.y, ya.z, ya.w, yb.x, yb.y, yb.z, yb.w};
#pragma unroll
        for (int i = 0; i < 8; i++) {
            amax = max(amax, av[i]);
            a0 += (av[i] == 0); a1 += (av[i] == 1);
            b0 += (bv[i] == 0); b1 += (bv[i] == 1);
        }
    }
#pragma unroll
    for (int d = 16; d > 0; d >>= 1)
        amax = max(amax, __shfl_xor_sync(0xffffffffu, amax, d));

    __shared__ int smax[16];
    __shared__ int s_a_is_grain;
    if (lane == 0) smax[warp] = amax;
    __syncthreads();
    if (t == 0) {
        int m = smax[0];
#pragma unroll
        for (int i = 1; i < 16; i++) m = max(m, smax[i]);
        s_a_is_grain = (m <= 2) ? 1 : 0;
    }
    __syncthreads();
    const bool a_is_grain = (s_a_is_grain != 0);

    const unsigned packed = a_is_grain ? (a0 | (a1 << 16)) : (b0 | (b1 << 16));

    // ---- block-wide exclusive scan of packed (16 warps) ----
    unsigned inc = packed;
#pragma unroll
    for (int d = 1; d < 32; d <<= 1) {
        unsigned n = __shfl_up_sync(0xffffffffu, inc, d);
        if (lane >= (unsigned)d) inc += n;
    }

    __shared__ unsigned warp_sums[16];
    __shared__ unsigned block_total;
    if (lane == 31) warp_sums[warp] = inc;
    __syncthreads();

    if (warp == 0 && lane < 16) {
        unsigned w = warp_sums[lane];
        unsigned wi = w;
#pragma unroll
        for (int d = 1; d < 16; d <<= 1) {
            unsigned n = __shfl_up_sync(0xffffu, wi, d);
            if (lane >= (unsigned)d) wi += n;
        }
        warp_sums[lane] = wi - w;
        if (lane == 15) block_total = wi;
    }
    __syncthreads();

    const unsigned ex = warp_sums[warp] + (inc - packed);
    const unsigned tot = block_total;

    const int cnt0 = (int)(tot & 0xFFFFu);
    const int cnt1 = (int)(tot >> 16);
    const int cnt2 = NTOK - cnt0 - cnt1;

    // per-class smem bases, each ≡ b_align (mod 4) so smem and gmem share phase
    const int base0 = b_align;
    const int base1 = ((base0 + cnt0 + 3) & ~3) + b_align;
    const int base2 = ((base1 + cnt1 + 3) & ~3) + b_align;

    int off0 = base0 + (int)(ex & 0xFFFFu);
    int off1 = base1 + (int)(ex >> 16);
    int off2 = base2 + (8 * t - (int)(ex & 0xFFFFu) - (int)(ex >> 16));

    // ---- phase 2: reload inputs (L1-hot) and scatter into SMEM ----
    {
        int4 xa = a4[t * 2 + 0];
        int4 xb = a4[t * 2 + 1];
        int4 ya = b4[t * 2 + 0];
        int4 yb = b4[t * 2 + 1];
        int av[8] = {xa.x, xa.y, xa.z, xa.w, xb.x, xb.y, xb.z, xb.w};
        int bv[8] = {ya.x, ya.y, ya.z, ya.w, yb.x, yb.y, yb.z, yb.w};
        const int pbase = t * 8;
#pragma unroll
        for (int i = 0; i < 8; i++) {
            const int g = a_is_grain ? av[i] : bv[i];
            const int v = a_is_grain ? bv[i] : av[i];
            int slot;
            if (g == 0)      { slot = off0++; }
            else if (g == 1) { slot = off1++; }
            else             { slot = off2++; }
            sval[slot]  = (float)v;
            sposn[slot] = (float)(pbase + i);
        }
    }
    __syncthreads();

    // ---- section base pointers for this row ----
    const long plane = (long)BATCH * NP1;
    const long rowb  = (long)b * NP1;
    float* cc  = out + 0 * plane + rowb;
    float* mc  = out + 1 * plane + rowb;
    float* fc  = out + 2 * plane + rowb;
    float* cp  = out + 3 * plane + rowb;
    float* mp  = out + 4 * plane + rowb;
    float* fp_ = out + 5 * plane + rowb;
    float* cs  = out + 6 * plane + rowb;
    float* ms  = out + 7 * plane + rowb;
    float* fs  = out + 8 * plane + rowb;

    // ---- paired coalesced writes (LDS.128 -> STG.128 in the bulk) ----
    copy_pair(cc,  cp,  sval + base0, sposn + base0, cnt0, t, b_align);
    tail_pair(cc,  cp,  cnt0, CONTENT_EOS, CONTENT_PAD, COARSE_POS_EOS, COARSE_POS_PAD, t, b_align);
    copy_pair(mc,  mp,  sval + base1, sposn + base1, cnt1, t, b_align);
    tail_pair(mc,  mp,  cnt1, CONTENT_EOS, CONTENT_PAD, MEDIUM_POS_EOS, MEDIUM_POS_PAD, t, b_align);
    copy_pair(fc,  fp_, sval + base2, sposn + base2, cnt2, t, b_align);
    tail_pair(fc,  fp_, cnt2, CONTENT_EOS, CONTENT_PAD, FINE_POS_EOS,   FINE_POS_PAD,   t, b_align);

    fill_const3(cs, ms, fs, t, b_align);
}

extern "C" void kernel_launch(void* const* d_in, const int* in_sizes, int n_in,
                              void* d_out, int out_size)
{
    const int* in0 = (const int*)d_in[0];
    const int* in1 = (const int*)d_in[1];
    float* out = (float*)d_out;
    triple_grain_kernel<<<BATCH, NTHR>>>(in0, in1, out);
}